// round 9
// baseline (speedup 1.0000x reference)
#include <cuda_runtime.h>
#include <cuda_bf16.h>

#define BN 512
#define VN 778
#define FN 1538
#define PN 1024
#define NRED 22

// Device scratch (no allocations allowed)
__device__ float g_part[NRED * BN];
__device__ unsigned int g_cnt = 0;

__device__ __forceinline__ float warpReduceSum(float v) {
#pragma unroll
    for (int o = 16; o > 0; o >>= 1) v += __shfl_down_sync(0xffffffffu, v, o);
    return v;
}

// phi = sum_k relu(-h_k) * exp(-2*rho2_k)   (sigma = 0.5)
__device__ __forceinline__ float coneFieldV(float4 t0, float4 t1, float4 t2,
                                            float4 q0, float4 q1, float4 q2) {
    const float third = 1.0f / 3.0f;
    float cx = (t0.x + t1.x + t2.x) * third;
    float cy = (t0.y + t1.y + t2.y) * third;
    float cz = (t0.z + t1.z + t2.z) * third;
    float e1x = t1.x - t0.x, e1y = t1.y - t0.y, e1z = t1.z - t0.z;
    float e2x = t2.x - t0.x, e2y = t2.y - t0.y, e2z = t2.z - t0.z;
    float nx = e1y * e2z - e1z * e2y;
    float ny = e1z * e2x - e1x * e2z;
    float nz = e1x * e2y - e1y * e2x;
    float inv = rsqrtf(nx * nx + ny * ny + nz * nz + 1e-18f);
    nx *= inv; ny *= inv; nz *= inv;

    float s = 0.0f;
    {
        float dx = q0.x - cx, dy = q0.y - cy, dz = q0.z - cz;
        float h = dx * nx + dy * ny + dz * nz;
        float rho2 = fmaxf(dx * dx + dy * dy + dz * dz - h * h, 0.0f);
        s += fmaxf(-h, 0.0f) * __expf(-2.0f * rho2);
    }
    {
        float dx = q1.x - cx, dy = q1.y - cy, dz = q1.z - cz;
        float h = dx * nx + dy * ny + dz * nz;
        float rho2 = fmaxf(dx * dx + dy * dy + dz * dz - h * h, 0.0f);
        s += fmaxf(-h, 0.0f) * __expf(-2.0f * rho2);
    }
    {
        float dx = q2.x - cx, dy = q2.y - cy, dz = q2.z - cz;
        float h = dx * nx + dy * ny + dz * nz;
        float rho2 = fmaxf(dx * dx + dy * dy + dz * dz - h * h, 0.0f);
        s += fmaxf(-h, 0.0f) * __expf(-2.0f * rho2);
    }
    return s;
}

// Dynamic smem: verts as float4 (2*VN) + packed faces (2*FN u32)
#define SMEM_BYTES (2 * VN * 16 + 2 * FN * 4)

__global__ void __launch_bounds__(512, 3)
fused_kernel(const float* __restrict__ verts,  const int* __restrict__ faces,
             const int* __restrict__ cidx,
             const float* __restrict__ betas,  const float* __restrict__ transl,
             const float* __restrict__ j3d,    const float* __restrict__ go,
             const float* __restrict__ pose,   const float* __restrict__ ttrans,
             const float* __restrict__ tj3d,   const float* __restrict__ tgo,
             const float* __restrict__ tpose,  const float* __restrict__ tshape,
             const float* __restrict__ logits, const int* __restrict__ handed,
             const int* __restrict__ valid,    const int* __restrict__ ctgt,
             float* __restrict__ out) {
    extern __shared__ char dyn[];
    float4* sv = (float4*)dyn;                         // 2*VN float4
    unsigned int* sfp = (unsigned int*)(sv + 2 * VN);  // 2*FN packed faces

    int b = blockIdx.x;
    int j = threadIdx.x;
    const float* v0 = verts + (size_t)b * VN * 3;
    const float* v1 = verts + (size_t)(BN + b) * VN * 3;

    // ---- prefetch pair indices (overlaps staging latency) ----
    int2 pi0 = __ldg((const int2*)(cidx + ((size_t)b * PN + j) * 2));
    int2 pi1 = __ldg((const int2*)(cidx + ((size_t)b * PN + j + 512) * 2));

    // ---- stage verts (float4 slots) ----
    for (int i = j; i < VN; i += 512) {
        const float* p = v0 + i * 3;
        sv[i] = make_float4(p[0], p[1], p[2], 0.0f);
        const float* q = v1 + i * 3;
        sv[VN + i] = make_float4(q[0], q[1], q[2], 0.0f);
    }
    // ---- stage faces packed (3 x 10-bit ids), vectorized: 3 int4 -> 4 faces ----
    // 2*FN = 3076 = 4*769 groups
    {
        const int4* f4 = (const int4*)faces;
        for (int g = j; g < 769; g += 512) {
            int4 a = __ldg(f4 + 3 * g);
            int4 c0 = __ldg(f4 + 3 * g + 1);
            int4 c1 = __ldg(f4 + 3 * g + 2);
            int fi = 4 * g;
            sfp[fi + 0] = (unsigned)a.x | ((unsigned)a.y << 10) | ((unsigned)a.z << 20);
            sfp[fi + 1] = (unsigned)a.w | ((unsigned)c0.x << 10) | ((unsigned)c0.y << 20);
            sfp[fi + 2] = (unsigned)c0.z | ((unsigned)c0.w << 10) | ((unsigned)c1.x << 20);
            sfp[fi + 3] = (unsigned)c1.y | ((unsigned)c1.z << 10) | ((unsigned)c1.w << 20);
        }
    }
    __syncthreads();

    // ---- collision (branchless, 2 pairs/thread, sequential to cap regs) ----
    float acc = 0.0f;
#pragma unroll
    for (int it = 0; it < 2; it++) {
        int2 ii = (it == 0) ? pi0 : pi1;
        float vmask = (ii.x >= 0 && ii.y >= 0) ? 1.0f : 0.0f;
        int fa = max(ii.x, 0);
        int fb = max(ii.y, 0);
        unsigned wa = sfp[fa];
        unsigned wb = sfp[fb];
        int offa = (fa >= FN) ? VN : 0;
        int offb = (fb >= FN) ? VN : 0;
        float4 A0 = sv[(wa & 1023u) + offa];
        float4 A1 = sv[((wa >> 10) & 1023u) + offa];
        float4 A2 = sv[((wa >> 20) & 1023u) + offa];
        float4 B0 = sv[(wb & 1023u) + offb];
        float4 B1 = sv[((wb >> 10) & 1023u) + offb];
        float4 B2 = sv[((wb >> 20) & 1023u) + offb];
        float pair = coneFieldV(A0, A1, A2, B0, B1, B2) +
                     coneFieldV(B0, B1, B2, A0, A1, A2);
        acc += vmask * pair;
    }

    __shared__ float swarp[16];
    __shared__ float s_lb;
    int wid = j >> 5;
    float w = warpReduceSum(acc);
    if ((j & 31) == 0) swarp[wid] = w;
    __syncthreads();
    if (j == 0) {
        float t = 0.0f;
#pragma unroll
        for (int i = 0; i < 16; i++) t += swarp[i];
        s_lb = t;
    }
    __syncthreads();

    // ---- per-batch small loss partials, element-parallel over j ----
    float a[NRED];
#pragma unroll
    for (int i = 0; i < NRED; i++) a[i] = 0.0f;

    if (j == 0) {
        float lb = s_lb;
        a[0] = lb;
        a[1] = (lb != 0.0f) ? 1.0f : 0.0f;
        float fint = ((__ldg(handed + b * 2) + __ldg(handed + b * 2 + 1)) == 2)
                         ? 1.0f : 0.0f;
        a[2] = fint;
    }
    float fint = ((__ldg(handed + b * 2) + __ldg(handed + b * 2 + 1)) == 2)
                     ? 1.0f : 0.0f;

    if (j < 10) {
        float d = betas[b * 10 + j] - betas[(BN + b) * 10 + j];
        a[3] = fint * d * d;
    }
    if (j < 3) {
        float d = (transl[b * 3 + j] - transl[(BN + b) * 3 + j]) -
                  (ttrans[b * 3 + j] - ttrans[(BN + b) * 3 + j]);
        a[4] = fint * d * d;
    }
    if (j < 63) {
        float d = (j3d[b * 63 + j] - j3d[(BN + b) * 63 + j]) -
                  (tj3d[b * 63 + j] - tj3d[(BN + b) * 63 + j]);
        a[5] = fint * d * d;
    }

#pragma unroll
    for (int h = 0; h < 2; h++) {
        int base = 6 + 7 * h;
        float m = (float)__ldg(valid + h * BN + b);
        if (j == 0) a[base + 0] = m;

        if (j < 3) {
            float d = go[(h * BN + b) * 3 + j] - tgo[(h * BN + b) * 3 + j];
            a[base + 1] = m * d * d;
        }
        if (j < 45) {
            float d = pose[(h * BN + b) * 45 + j] - tpose[(h * BN + b) * 45 + j];
            a[base + 2] = m * d * d;
        }
        if (j < 63) {
            const float* jo = j3d  + (size_t)(h * BN + b) * 63;
            const float* jt = tj3d + (size_t)(h * BN + b) * 63;
            float o = jo[j], t = jt[j];
            if (j >= 3) {
                int c = j % 3;
                float d = (o - jo[c]) * 1000.0f - (t - jt[c]) * 1000.0f;
                a[base + 3] = m * fabsf(d);
            }
            a[base + 4] = m * fabsf(o * 1000.0f - t * 1000.0f);
        }
        if (j < 10) {
            float d = betas[(h * BN + b) * 10 + j] - tshape[(h * BN + b) * 10 + j];
            a[base + 5] = m * d * d;
        }
        if (j < 3) {
            float d = transl[(h * BN + b) * 3 + j] - ttrans[(h * BN + b) * 3 + j];
            a[base + 6] = m * fabsf(d);
        }
    }

    if (j == 0) {
        const float* lg = logits + b * 4;
        float l0 = lg[0], l1 = lg[1], l2 = lg[2], l3 = lg[3];
        float mx = fmaxf(fmaxf(l0, l1), fmaxf(l2, l3));
        float se = __expf(l0 - mx) + __expf(l1 - mx) + __expf(l2 - mx) + __expf(l3 - mx);
        float lse = logf(se);
        int t = __ldg(ctgt + b);
        float lt = (t == 0) ? l0 : (t == 1) ? l1 : (t == 2) ? l2 : l3;
        float nll = -(lt - mx - lse);
        const float wts[4] = {1.0f, 30.0f, 30.0f, 10.0f};
        float wv = wts[t] * ((t != 0) ? 1.0f : 0.0f);
        a[20] = wv * nll;
        a[21] = wv;
    }

    // block-reduce the 22 slots (16 warps)
    __shared__ float red[NRED][16];
#pragma unroll
    for (int i = 0; i < NRED; i++) {
        float v = warpReduceSum(a[i]);
        if ((j & 31) == 0) red[i][wid] = v;
    }
    __syncthreads();
    if (j < NRED) {
        float t = 0.0f;
#pragma unroll
        for (int k = 0; k < 16; k++) t += red[j][k];
        g_part[j * BN + b] = t;
    }

    // ---- last block folds the final reduction ----
    __threadfence();
    __syncthreads();
    __shared__ bool isLast;
    if (j == 0)
        isLast = (atomicAdd(&g_cnt, 1u) == (unsigned)(gridDim.x - 1));
    __syncthreads();
    if (!isLast) return;
    __threadfence();  // acquire all blocks' g_part writes

    float r[NRED];
#pragma unroll
    for (int i = 0; i < NRED; i++)
        r[i] = g_part[i * BN + j];

    __syncthreads();  // reuse red[][] safely
#pragma unroll
    for (int i = 0; i < NRED; i++) {
        float v = warpReduceSum(r[i]);
        if ((j & 31) == 0) red[i][wid] = v;
    }
    __syncthreads();

    if (j == 0) {
        g_cnt = 0;  // reset for next graph replay
        float s[NRED];
#pragma unroll
        for (int i = 0; i < NRED; i++) {
            float t = 0.0f;
#pragma unroll
            for (int k = 0; k < 16; k++) t += red[i][k];
            s[i] = t;
        }
        auto il = [](float sum, float denom) -> float {
            return (denom > 0.0f) ? sum / fmaxf(denom, 1.0f) : 0.0f;
        };

        out[0] = (s[1] > 0.0f) ? (s[0] / fmaxf(s[1], 1.0f)) * 100.0f : 0.0f;
        float ic = s[2];
        out[1] = il(s[3], ic * 10.0f);
        out[2] = il(s[4], ic * 3.0f) * 100.0f;
        out[3] = il(s[5], ic * 63.0f) * 100.0f;

        float lgo = 0, lhp = 0, lrj = 0, lj3 = 0, lsh = 0, ltr = 0;
#pragma unroll
        for (int h = 0; h < 2; h++) {
            int base = 6 + 7 * h;
            float c = s[base + 0];
            lgo += il(s[base + 1], c * 3.0f)  * 10.0f;
            lhp += il(s[base + 2], c * 45.0f) * 10.0f;
            lrj += il(s[base + 3], c * 60.0f) * 0.01f;
            lj3 += il(s[base + 4], c * 63.0f) * 0.01f;
            lsh += il(s[base + 5], c * 10.0f) * 10.0f;
            ltr += il(s[base + 6], c * 3.0f)  * 10.0f;
        }
        out[4] = lgo;
        out[5] = lhp;
        out[6] = lrj;
        out[7] = lj3;
        out[8] = lsh;
        out[9] = ltr;
        out[10] = 0.0f;  // mse(x,x) == 0 exactly
        out[11] = s[20] / fmaxf(s[21], 1e-9f);
    }
}

extern "C" void kernel_launch(void* const* d_in, const int* in_sizes, int n_in,
                              void* d_out, int out_size) {
    const float* verts  = (const float*)d_in[0];
    const float* betas  = (const float*)d_in[1];
    const float* transl = (const float*)d_in[2];
    const float* j3d    = (const float*)d_in[3];
    const float* go     = (const float*)d_in[4];
    const float* pose   = (const float*)d_in[5];
    const float* ttrans = (const float*)d_in[6];
    const float* tj3d   = (const float*)d_in[7];
    const float* tgo    = (const float*)d_in[8];
    const float* tpose  = (const float*)d_in[9];
    const float* tshape = (const float*)d_in[10];
    const float* logits = (const float*)d_in[11];
    const int*   faces  = (const int*)d_in[12];
    const int*   cidx   = (const int*)d_in[13];
    const int*   handed = (const int*)d_in[14];
    const int*   valid  = (const int*)d_in[15];
    const int*   ctgt   = (const int*)d_in[16];

    fused_kernel<<<BN, 512, SMEM_BYTES>>>(verts, faces, cidx, betas, transl,
                                          j3d, go, pose, ttrans, tj3d, tgo,
                                          tpose, tshape, logits, handed, valid,
                                          ctgt, (float*)d_out);
}

// round 10
// speedup vs baseline: 1.1774x; 1.1774x over previous
#include <cuda_runtime.h>
#include <cuda_bf16.h>

#define BN 512
#define VN 778
#define FN 1538
#define PN 1024
#define NRED 22
#define GRID 128
#define TPB 512
#define BPB 4   // batches per block: 512 = 128 * 4

// Device scratch (no allocations allowed)
__device__ float g_part[NRED * BN];
__device__ unsigned int g_cnt = 0;

__device__ __forceinline__ float warpReduceSum(float v) {
#pragma unroll
    for (int o = 16; o > 0; o >>= 1) v += __shfl_down_sync(0xffffffffu, v, o);
    return v;
}

// phi = sum_k relu(-h_k) * exp(-2*rho2_k)   (sigma = 0.5)
__device__ __forceinline__ float coneFieldV(float4 t0, float4 t1, float4 t2,
                                            float4 q0, float4 q1, float4 q2) {
    const float third = 1.0f / 3.0f;
    float cx = (t0.x + t1.x + t2.x) * third;
    float cy = (t0.y + t1.y + t2.y) * third;
    float cz = (t0.z + t1.z + t2.z) * third;
    float e1x = t1.x - t0.x, e1y = t1.y - t0.y, e1z = t1.z - t0.z;
    float e2x = t2.x - t0.x, e2y = t2.y - t0.y, e2z = t2.z - t0.z;
    float nx = e1y * e2z - e1z * e2y;
    float ny = e1z * e2x - e1x * e2z;
    float nz = e1x * e2y - e1y * e2x;
    float inv = rsqrtf(nx * nx + ny * ny + nz * nz + 1e-18f);
    nx *= inv; ny *= inv; nz *= inv;

    float s = 0.0f;
    {
        float dx = q0.x - cx, dy = q0.y - cy, dz = q0.z - cz;
        float h = dx * nx + dy * ny + dz * nz;
        float rho2 = fmaxf(dx * dx + dy * dy + dz * dz - h * h, 0.0f);
        s += fmaxf(-h, 0.0f) * __expf(-2.0f * rho2);
    }
    {
        float dx = q1.x - cx, dy = q1.y - cy, dz = q1.z - cz;
        float h = dx * nx + dy * ny + dz * nz;
        float rho2 = fmaxf(dx * dx + dy * dy + dz * dz - h * h, 0.0f);
        s += fmaxf(-h, 0.0f) * __expf(-2.0f * rho2);
    }
    {
        float dx = q2.x - cx, dy = q2.y - cy, dz = q2.z - cz;
        float h = dx * nx + dy * ny + dz * nz;
        float rho2 = fmaxf(dx * dx + dy * dy + dz * dz - h * h, 0.0f);
        s += fmaxf(-h, 0.0f) * __expf(-2.0f * rho2);
    }
    return s;
}

// Dynamic smem: 2 vert buffers (2*VN float4 each) + packed faces (2*FN u32)
#define SMEM_BYTES (2 * (2 * VN) * 16 + 2 * FN * 4)

__global__ void __launch_bounds__(TPB, 1)
fused_kernel(const float* __restrict__ verts,  const int* __restrict__ faces,
             const int* __restrict__ cidx,
             const float* __restrict__ betas,  const float* __restrict__ transl,
             const float* __restrict__ j3d,    const float* __restrict__ go,
             const float* __restrict__ pose,   const float* __restrict__ ttrans,
             const float* __restrict__ tj3d,   const float* __restrict__ tgo,
             const float* __restrict__ tpose,  const float* __restrict__ tshape,
             const float* __restrict__ logits, const int* __restrict__ handed,
             const int* __restrict__ valid,    const int* __restrict__ ctgt,
             float* __restrict__ out) {
    extern __shared__ char dyn[];
    float4* sv = (float4*)dyn;                             // [2][2*VN]
    unsigned int* sfp = (unsigned int*)(sv + 2 * (2 * VN));  // [2*FN]

    __shared__ float swarpS[2][16];
    __shared__ float redS[2][NRED][2];
    __shared__ float foldS[NRED][16];

    int blk = blockIdx.x;
    int j = threadIdx.x;
    int wid = j >> 5;
    int lane = j & 31;
    int b0 = blk * BPB;

    // ---- stage faces once: packed 3 x 10-bit ids. 2*FN = 3076 = 4*769 ----
    {
        const int4* f4 = (const int4*)faces;
        for (int g = j; g < 769; g += TPB) {
            int4 a0 = __ldg(f4 + 3 * g);
            int4 a1 = __ldg(f4 + 3 * g + 1);
            int4 a2 = __ldg(f4 + 3 * g + 2);
            int fi = 4 * g;
            sfp[fi + 0] = (unsigned)a0.x | ((unsigned)a0.y << 10) | ((unsigned)a0.z << 20);
            sfp[fi + 1] = (unsigned)a0.w | ((unsigned)a1.x << 10) | ((unsigned)a1.y << 20);
            sfp[fi + 2] = (unsigned)a1.z | ((unsigned)a1.w << 10) | ((unsigned)a2.x << 20);
            sfp[fi + 3] = (unsigned)a2.y | ((unsigned)a2.z << 10) | ((unsigned)a2.w << 20);
        }
    }

    // ---- prologue: stage verts for batch b0 into buffer 0 ----
    {
        const float* v0 = verts + (size_t)b0 * VN * 3;
        const float* v1 = verts + (size_t)(BN + b0) * VN * 3;
        float4 a = make_float4(__ldg(v0 + j * 3), __ldg(v0 + j * 3 + 1),
                               __ldg(v0 + j * 3 + 2), 0.0f);
        float4 c = make_float4(__ldg(v1 + j * 3), __ldg(v1 + j * 3 + 1),
                               __ldg(v1 + j * 3 + 2), 0.0f);
        sv[j] = a;
        sv[VN + j] = c;
        if (j < VN - TPB) {
            float4 bq = make_float4(__ldg(v0 + (TPB + j) * 3), __ldg(v0 + (TPB + j) * 3 + 1),
                                    __ldg(v0 + (TPB + j) * 3 + 2), 0.0f);
            float4 d = make_float4(__ldg(v1 + (TPB + j) * 3), __ldg(v1 + (TPB + j) * 3 + 1),
                                   __ldg(v1 + (TPB + j) * 3 + 2), 0.0f);
            sv[TPB + j] = bq;
            sv[VN + TPB + j] = d;
        }
    }
    int2 pc0 = __ldg((const int2*)(cidx + ((size_t)b0 * PN + j) * 2));
    int2 pc1 = __ldg((const int2*)(cidx + ((size_t)b0 * PN + j + TPB) * 2));
    __syncthreads();

    for (int i = 0; i < BPB; i++) {
        int b = b0 + i;
        int cur = i & 1;

        // ---- finalize previous batch's reductions (reads prev-parity bufs) ----
        if (i > 0) {
            int pp = (i - 1) & 1;
            int bp = b - 1;
            if (j == 0) {
                float t = 0.0f;
#pragma unroll
                for (int k = 0; k < 16; k++) t += swarpS[pp][k];
                g_part[0 * BN + bp] = t;
                g_part[1 * BN + bp] = (t != 0.0f) ? 1.0f : 0.0f;
            }
            if (j >= 2 && j < NRED)
                g_part[j * BN + bp] = redS[pp][j][0] + redS[pp][j][1];
        }

        // ---- prefetch next batch verts + cidx into registers ----
        float4 nva, nvb, nvc, nvd;
        int2 nc0 = make_int2(0, 0), nc1 = make_int2(0, 0);
        if (i + 1 < BPB) {
            int bn = b + 1;
            const float* v0 = verts + (size_t)bn * VN * 3;
            const float* v1 = verts + (size_t)(BN + bn) * VN * 3;
            nva = make_float4(__ldg(v0 + j * 3), __ldg(v0 + j * 3 + 1),
                              __ldg(v0 + j * 3 + 2), 0.0f);
            nvc = make_float4(__ldg(v1 + j * 3), __ldg(v1 + j * 3 + 1),
                              __ldg(v1 + j * 3 + 2), 0.0f);
            if (j < VN - TPB) {
                nvb = make_float4(__ldg(v0 + (TPB + j) * 3), __ldg(v0 + (TPB + j) * 3 + 1),
                                  __ldg(v0 + (TPB + j) * 3 + 2), 0.0f);
                nvd = make_float4(__ldg(v1 + (TPB + j) * 3), __ldg(v1 + (TPB + j) * 3 + 1),
                                  __ldg(v1 + (TPB + j) * 3 + 2), 0.0f);
            }
            nc0 = __ldg((const int2*)(cidx + ((size_t)bn * PN + j) * 2));
            nc1 = __ldg((const int2*)(cidx + ((size_t)bn * PN + j + TPB) * 2));
        }

        // ---- prefetch small-loss inputs for current batch (warps 0-1) ----
        float fint = 0, m0 = 0, m1 = 0;
        float bet0 = 0, bet1 = 0, tsh0 = 0, tsh1 = 0;
        float tr0 = 0, tr1 = 0, tt0 = 0, tt1 = 0;
        float ja = 0, jb1 = 0, ta = 0, tb = 0;
        float joc0 = 0, joc1 = 0, jtc0 = 0, jtc1 = 0;
        float go0 = 0, go1 = 0, tgo0 = 0, tgo1 = 0;
        float ps0 = 0, ps1 = 0, tps0 = 0, tps1 = 0;
        float l0 = 0, l1 = 0, l2 = 0, l3 = 0;
        int ct = 0;
        if (j < 64) {
            int h0 = __ldg(handed + b * 2);
            int h1 = __ldg(handed + b * 2 + 1);
            fint = ((h0 + h1) == 2) ? 1.0f : 0.0f;
            m0 = (float)__ldg(valid + b);
            m1 = (float)__ldg(valid + BN + b);
            if (j < 10) {
                bet0 = __ldg(betas + b * 10 + j);
                bet1 = __ldg(betas + (BN + b) * 10 + j);
                tsh0 = __ldg(tshape + b * 10 + j);
                tsh1 = __ldg(tshape + (BN + b) * 10 + j);
            }
            if (j < 3) {
                tr0 = __ldg(transl + b * 3 + j);
                tr1 = __ldg(transl + (BN + b) * 3 + j);
                tt0 = __ldg(ttrans + b * 3 + j);
                tt1 = __ldg(ttrans + (BN + b) * 3 + j);
                go0 = __ldg(go + b * 3 + j);
                go1 = __ldg(go + (BN + b) * 3 + j);
                tgo0 = __ldg(tgo + b * 3 + j);
                tgo1 = __ldg(tgo + (BN + b) * 3 + j);
            }
            if (j < 45) {
                ps0 = __ldg(pose + b * 45 + j);
                ps1 = __ldg(pose + (BN + b) * 45 + j);
                tps0 = __ldg(tpose + b * 45 + j);
                tps1 = __ldg(tpose + (BN + b) * 45 + j);
            }
            if (j < 63) {
                int c = j % 3;
                ja  = __ldg(j3d + b * 63 + j);
                jb1 = __ldg(j3d + (size_t)(BN + b) * 63 + j);
                ta  = __ldg(tj3d + b * 63 + j);
                tb  = __ldg(tj3d + (size_t)(BN + b) * 63 + j);
                joc0 = __ldg(j3d + b * 63 + c);
                joc1 = __ldg(j3d + (size_t)(BN + b) * 63 + c);
                jtc0 = __ldg(tj3d + b * 63 + c);
                jtc1 = __ldg(tj3d + (size_t)(BN + b) * 63 + c);
            }
            if (j == 0) {
                l0 = __ldg(logits + b * 4 + 0);
                l1 = __ldg(logits + b * 4 + 1);
                l2 = __ldg(logits + b * 4 + 2);
                l3 = __ldg(logits + b * 4 + 3);
                ct = __ldg(ctgt + b);
            }
        }

        // ---- collision: 2 pairs/thread from current buffer ----
        const float4* svc = sv + cur * (2 * VN);
        float acc = 0.0f;
#pragma unroll
        for (int it = 0; it < 2; it++) {
            int2 ii = (it == 0) ? pc0 : pc1;
            float vmask = (ii.x >= 0 && ii.y >= 0) ? 1.0f : 0.0f;
            int fa = max(ii.x, 0);
            int fb = max(ii.y, 0);
            unsigned wa = sfp[fa];
            unsigned wb = sfp[fb];
            int offa = (fa >= FN) ? VN : 0;
            int offb = (fb >= FN) ? VN : 0;
            float4 A0 = svc[(wa & 1023u) + offa];
            float4 A1 = svc[((wa >> 10) & 1023u) + offa];
            float4 A2 = svc[((wa >> 20) & 1023u) + offa];
            float4 B0 = svc[(wb & 1023u) + offb];
            float4 B1 = svc[((wb >> 10) & 1023u) + offb];
            float4 B2 = svc[((wb >> 20) & 1023u) + offb];
            float pair = coneFieldV(A0, A1, A2, B0, B1, B2) +
                         coneFieldV(B0, B1, B2, A0, A1, A2);
            acc += vmask * pair;
        }

        // collision block-partial
        float w = warpReduceSum(acc);
        if (lane == 0) swarpS[cur][wid] = w;

        // ---- small-loss partials (warps 0-1 only), reduce into redS[cur] ----
        if (j < 64) {
            float a[NRED];
#pragma unroll
            for (int k = 0; k < NRED; k++) a[k] = 0.0f;

            if (j == 0) a[2] = fint;
            if (j < 10) { float d = bet0 - bet1; a[3] = fint * d * d; }
            if (j < 3)  { float d = (tr0 - tr1) - (tt0 - tt1); a[4] = fint * d * d; }
            if (j < 63) { float d = (ja - jb1) - (ta - tb); a[5] = fint * d * d; }

#pragma unroll
            for (int h = 0; h < 2; h++) {
                int base = 6 + 7 * h;
                float m = (h == 0) ? m0 : m1;
                float o   = (h == 0) ? ja : jb1;
                float t   = (h == 0) ? ta : tb;
                float joc = (h == 0) ? joc0 : joc1;
                float jtc = (h == 0) ? jtc0 : jtc1;
                if (j == 0) a[base + 0] = m;
                if (j < 3) {
                    float d = ((h == 0) ? go0 : go1) - ((h == 0) ? tgo0 : tgo1);
                    a[base + 1] = m * d * d;
                }
                if (j < 45) {
                    float d = ((h == 0) ? ps0 : ps1) - ((h == 0) ? tps0 : tps1);
                    a[base + 2] = m * d * d;
                }
                if (j >= 3 && j < 63) {
                    float d = (o - joc) * 1000.0f - (t - jtc) * 1000.0f;
                    a[base + 3] = m * fabsf(d);
                }
                if (j < 63)
                    a[base + 4] = m * fabsf(o * 1000.0f - t * 1000.0f);
                if (j < 10) {
                    float d = ((h == 0) ? bet0 : bet1) - ((h == 0) ? tsh0 : tsh1);
                    a[base + 5] = m * d * d;
                }
                if (j < 3) {
                    float d = ((h == 0) ? tr0 : tr1) - ((h == 0) ? tt0 : tt1);
                    a[base + 6] = m * fabsf(d);
                }
            }

            if (j == 0) {
                float mx = fmaxf(fmaxf(l0, l1), fmaxf(l2, l3));
                float se = __expf(l0 - mx) + __expf(l1 - mx) +
                           __expf(l2 - mx) + __expf(l3 - mx);
                float lse = logf(se);
                float lt = (ct == 0) ? l0 : (ct == 1) ? l1 : (ct == 2) ? l2 : l3;
                float nll = -(lt - mx - lse);
                const float wts[4] = {1.0f, 30.0f, 30.0f, 10.0f};
                float wv = wts[ct] * ((ct != 0) ? 1.0f : 0.0f);
                a[20] = wv * nll;
                a[21] = wv;
            }

#pragma unroll
            for (int s = 2; s < NRED; s++) {
                float v = warpReduceSum(a[s]);
                if (lane == 0) redS[cur][s][wid] = v;
            }
        }

        // ---- store next batch verts into the other buffer ----
        if (i + 1 < BPB) {
            float4* svn = sv + ((i + 1) & 1) * (2 * VN);
            svn[j] = nva;
            svn[VN + j] = nvc;
            if (j < VN - TPB) {
                svn[TPB + j] = nvb;
                svn[VN + TPB + j] = nvd;
            }
        }
        __syncthreads();
        pc0 = nc0;
        pc1 = nc1;
    }

    // ---- finalize last batch (parity (BPB-1)&1 = 1) ----
    {
        int bp = b0 + BPB - 1;
        if (j == 0) {
            float t = 0.0f;
#pragma unroll
            for (int k = 0; k < 16; k++) t += swarpS[1][k];
            g_part[0 * BN + bp] = t;
            g_part[1 * BN + bp] = (t != 0.0f) ? 1.0f : 0.0f;
        }
        if (j >= 2 && j < NRED)
            g_part[j * BN + bp] = redS[1][j][0] + redS[1][j][1];
    }

    // ---- last block folds the final reduction ----
    __threadfence();
    __syncthreads();
    __shared__ bool isLast;
    if (j == 0)
        isLast = (atomicAdd(&g_cnt, 1u) == (unsigned)(GRID - 1));
    __syncthreads();
    if (!isLast) return;
    __threadfence();  // acquire all blocks' g_part writes

    float r[NRED];
#pragma unroll
    for (int k = 0; k < NRED; k++)
        r[k] = g_part[k * BN + j];

#pragma unroll
    for (int k = 0; k < NRED; k++) {
        float v = warpReduceSum(r[k]);
        if (lane == 0) foldS[k][wid] = v;
    }
    __syncthreads();

    if (j == 0) {
        g_cnt = 0;  // reset for next graph replay
        float s[NRED];
#pragma unroll
        for (int k = 0; k < NRED; k++) {
            float t = 0.0f;
#pragma unroll
            for (int q = 0; q < 16; q++) t += foldS[k][q];
            s[k] = t;
        }
        auto il = [](float sum, float denom) -> float {
            return (denom > 0.0f) ? sum / fmaxf(denom, 1.0f) : 0.0f;
        };

        out[0] = (s[1] > 0.0f) ? (s[0] / fmaxf(s[1], 1.0f)) * 100.0f : 0.0f;
        float ic = s[2];
        out[1] = il(s[3], ic * 10.0f);
        out[2] = il(s[4], ic * 3.0f) * 100.0f;
        out[3] = il(s[5], ic * 63.0f) * 100.0f;

        float lgo = 0, lhp = 0, lrj = 0, lj3 = 0, lsh = 0, ltr = 0;
#pragma unroll
        for (int h = 0; h < 2; h++) {
            int base = 6 + 7 * h;
            float c = s[base + 0];
            lgo += il(s[base + 1], c * 3.0f)  * 10.0f;
            lhp += il(s[base + 2], c * 45.0f) * 10.0f;
            lrj += il(s[base + 3], c * 60.0f) * 0.01f;
            lj3 += il(s[base + 4], c * 63.0f) * 0.01f;
            lsh += il(s[base + 5], c * 10.0f) * 10.0f;
            ltr += il(s[base + 6], c * 3.0f)  * 10.0f;
        }
        out[4] = lgo;
        out[5] = lhp;
        out[6] = lrj;
        out[7] = lj3;
        out[8] = lsh;
        out[9] = ltr;
        out[10] = 0.0f;  // mse(x,x) == 0 exactly
        out[11] = s[20] / fmaxf(s[21], 1e-9f);
    }
}

extern "C" void kernel_launch(void* const* d_in, const int* in_sizes, int n_in,
                              void* d_out, int out_size) {
    const float* verts  = (const float*)d_in[0];
    const float* betas  = (const float*)d_in[1];
    const float* transl = (const float*)d_in[2];
    const float* j3d    = (const float*)d_in[3];
    const float* go     = (const float*)d_in[4];
    const float* pose   = (const float*)d_in[5];
    const float* ttrans = (const float*)d_in[6];
    const float* tj3d   = (const float*)d_in[7];
    const float* tgo    = (const float*)d_in[8];
    const float* tpose  = (const float*)d_in[9];
    const float* tshape = (const float*)d_in[10];
    const float* logits = (const float*)d_in[11];
    const int*   faces  = (const int*)d_in[12];
    const int*   cidx   = (const int*)d_in[13];
    const int*   handed = (const int*)d_in[14];
    const int*   valid  = (const int*)d_in[15];
    const int*   ctgt   = (const int*)d_in[16];

    static bool attr_set = false;
    if (!attr_set) {
        cudaFuncSetAttribute(fused_kernel,
                             cudaFuncAttributeMaxDynamicSharedMemorySize,
                             SMEM_BYTES);
        attr_set = true;
    }

    fused_kernel<<<GRID, TPB, SMEM_BYTES>>>(verts, faces, cidx, betas, transl,
                                            j3d, go, pose, ttrans, tj3d, tgo,
                                            tpose, tshape, logits, handed, valid,
                                            ctgt, (float*)d_out);
}

// round 11
// speedup vs baseline: 1.1954x; 1.0153x over previous
#include <cuda_runtime.h>
#include <cuda_bf16.h>

#define BN 512
#define VN 778
#define FN 1538
#define PN 1024
#define NRED 22

typedef unsigned long long u64;

// Device scratch (no allocations allowed)
__device__ float g_part[NRED * BN];
__device__ unsigned int g_cnt = 0;

__device__ __forceinline__ float warpReduceSum(float v) {
#pragma unroll
    for (int o = 16; o > 0; o >>= 1) v += __shfl_down_sync(0xffffffffu, v, o);
    return v;
}

// ---- packed f32x2 helpers (Blackwell PTX-only ops) ----
__device__ __forceinline__ u64 pk2(float lo, float hi) {
    u64 r; asm("mov.b64 %0, {%1, %2};" : "=l"(r) : "f"(lo), "f"(hi)); return r;
}
__device__ __forceinline__ void upk2(float& lo, float& hi, u64 v) {
    asm("mov.b64 {%0, %1}, %2;" : "=f"(lo), "=f"(hi) : "l"(v));
}
__device__ __forceinline__ u64 f2fma(u64 a, u64 b, u64 c) {
    u64 d; asm("fma.rn.f32x2 %0, %1, %2, %3;" : "=l"(d) : "l"(a), "l"(b), "l"(c)); return d;
}
__device__ __forceinline__ u64 f2mul(u64 a, u64 b) {
    u64 d; asm("mul.rn.f32x2 %0, %1, %2;" : "=l"(d) : "l"(a), "l"(b)); return d;
}
__device__ __forceinline__ u64 f2add(u64 a, u64 b) {
    u64 d; asm("add.rn.f32x2 %0, %1, %2;" : "=l"(d) : "l"(a), "l"(b)); return d;
}

// Both cone fields of one pair, SIMD-packed: lane0 = coneField(A,B), lane1 = coneField(B,A).
// Returns phi1 + phi2.  exp(-2*rho2) == exp2(rho2 * K2), K2 = -2/ln(2).
__device__ __forceinline__ float pairPhi(float4 A0, float4 A1, float4 A2,
                                         float4 B0, float4 B1, float4 B2) {
    const u64 NEG1 = pk2(-1.0f, -1.0f);
    const u64 TH   = pk2(1.0f / 3.0f, 1.0f / 3.0f);
    const float K2 = -2.8853900817779268f;

    // packed tri verts: lane0 = A (tri of field1), lane1 = B (tri of field2)
    u64 t0x = pk2(A0.x, B0.x), t0y = pk2(A0.y, B0.y), t0z = pk2(A0.z, B0.z);
    u64 t1x = pk2(A1.x, B1.x), t1y = pk2(A1.y, B1.y), t1z = pk2(A1.z, B1.z);
    u64 t2x = pk2(A2.x, B2.x), t2y = pk2(A2.y, B2.y), t2z = pk2(A2.z, B2.z);

    u64 cx = f2mul(f2add(f2add(t0x, t1x), t2x), TH);
    u64 cy = f2mul(f2add(f2add(t0y, t1y), t2y), TH);
    u64 cz = f2mul(f2add(f2add(t0z, t1z), t2z), TH);

    u64 e1x = f2fma(t0x, NEG1, t1x), e1y = f2fma(t0y, NEG1, t1y), e1z = f2fma(t0z, NEG1, t1z);
    u64 e2x = f2fma(t0x, NEG1, t2x), e2y = f2fma(t0y, NEG1, t2y), e2z = f2fma(t0z, NEG1, t2z);

    u64 nx = f2fma(e1y, e2z, f2mul(f2mul(e1z, e2y), NEG1));
    u64 ny = f2fma(e1z, e2x, f2mul(f2mul(e1x, e2z), NEG1));
    u64 nz = f2fma(e1x, e2y, f2mul(f2mul(e1y, e2x), NEG1));

    u64 nn = f2fma(nx, nx, f2fma(ny, ny, f2mul(nz, nz)));
    float n1, n2; upk2(n1, n2, nn);
    u64 inv = pk2(rsqrtf(n1 + 1e-18f), rsqrtf(n2 + 1e-18f));
    nx = f2mul(nx, inv); ny = f2mul(ny, inv); nz = f2mul(nz, inv);

    float acc = 0.0f;
    // pts: lane0 = B verts, lane1 = A verts (swapped halves)
#define CF_POINT(PA, PB)                                                        \
    {                                                                           \
        u64 qx = pk2(PB.x, PA.x), qy = pk2(PB.y, PA.y), qz = pk2(PB.z, PA.z);   \
        u64 dx = f2fma(cx, NEG1, qx);                                           \
        u64 dy = f2fma(cy, NEG1, qy);                                           \
        u64 dz = f2fma(cz, NEG1, qz);                                           \
        u64 h  = f2fma(dx, nx, f2fma(dy, ny, f2mul(dz, nz)));                   \
        u64 dd = f2fma(dx, dx, f2fma(dy, dy, f2mul(dz, dz)));                   \
        u64 nh = f2mul(h, NEG1);                                                \
        u64 rh = f2fma(h, nh, dd);                                              \
        float nh1, nh2, r1, r2;                                                 \
        upk2(nh1, nh2, nh); upk2(r1, r2, rh);                                   \
        acc += fmaxf(nh1, 0.0f) * exp2f(fmaxf(r1, 0.0f) * K2);                  \
        acc += fmaxf(nh2, 0.0f) * exp2f(fmaxf(r2, 0.0f) * K2);                  \
    }
    CF_POINT(A0, B0)
    CF_POINT(A1, B1)
    CF_POINT(A2, B2)
#undef CF_POINT
    return acc;
}

// Dynamic smem: verts as float4 (2*VN) + packed faces (2*FN u32)
#define SMEM_BYTES (2 * VN * 16 + 2 * FN * 4)

__global__ void __launch_bounds__(256, 4)
fused_kernel(const float* __restrict__ verts,  const int* __restrict__ faces,
             const int* __restrict__ cidx,
             const float* __restrict__ betas,  const float* __restrict__ transl,
             const float* __restrict__ j3d,    const float* __restrict__ go,
             const float* __restrict__ pose,   const float* __restrict__ ttrans,
             const float* __restrict__ tj3d,   const float* __restrict__ tgo,
             const float* __restrict__ tpose,  const float* __restrict__ tshape,
             const float* __restrict__ logits, const int* __restrict__ handed,
             const int* __restrict__ valid,    const int* __restrict__ ctgt,
             float* __restrict__ out) {
    extern __shared__ char dyn[];
    float4* sv = (float4*)dyn;                         // 2*VN float4
    unsigned int* sfp = (unsigned int*)(sv + 2 * VN);  // 2*FN packed faces

    int b = blockIdx.x;
    int j = threadIdx.x;
    const float* v0 = verts + (size_t)b * VN * 3;
    const float* v1 = verts + (size_t)(BN + b) * VN * 3;

    // ---- prefetch pair indices (overlaps staging latency) ----
    int2 pi[4];
#pragma unroll
    for (int it = 0; it < 4; it++)
        pi[it] = __ldg((const int2*)(cidx + ((size_t)b * PN + j + it * 256) * 2));

    // ---- stage verts (float4 slots) ----
    for (int i = j; i < VN; i += 256) {
        const float* p = v0 + i * 3;
        sv[i] = make_float4(p[0], p[1], p[2], 0.0f);
        const float* q = v1 + i * 3;
        sv[VN + i] = make_float4(q[0], q[1], q[2], 0.0f);
    }
    // ---- stage faces packed (3 x 10-bit ids), vectorized: 3 int4 -> 4 faces ----
    {
        const int4* f4 = (const int4*)faces;
        for (int g = j; g < 769; g += 256) {
            int4 a = __ldg(f4 + 3 * g);
            int4 c0 = __ldg(f4 + 3 * g + 1);
            int4 c1 = __ldg(f4 + 3 * g + 2);
            int fi = 4 * g;
            sfp[fi + 0] = (unsigned)a.x | ((unsigned)a.y << 10) | ((unsigned)a.z << 20);
            sfp[fi + 1] = (unsigned)a.w | ((unsigned)c0.x << 10) | ((unsigned)c0.y << 20);
            sfp[fi + 2] = (unsigned)c0.z | ((unsigned)c0.w << 10) | ((unsigned)c1.x << 20);
            sfp[fi + 3] = (unsigned)c1.y | ((unsigned)c1.z << 10) | ((unsigned)c1.w << 20);
        }
    }
    __syncthreads();

    // ---- collision (branchless, 4 pairs/thread, packed dual cone field) ----
    float acc = 0.0f;
#pragma unroll
    for (int it = 0; it < 4; it++) {
        int2 ii = pi[it];
        float vmask = (ii.x >= 0 && ii.y >= 0) ? 1.0f : 0.0f;
        int fa = max(ii.x, 0);
        int fb = max(ii.y, 0);
        unsigned wa = sfp[fa];
        unsigned wb = sfp[fb];
        int offa = (fa >= FN) ? VN : 0;
        int offb = (fb >= FN) ? VN : 0;
        float4 A0 = sv[(wa & 1023u) + offa];
        float4 A1 = sv[((wa >> 10) & 1023u) + offa];
        float4 A2 = sv[((wa >> 20) & 1023u) + offa];
        float4 B0 = sv[(wb & 1023u) + offb];
        float4 B1 = sv[((wb >> 10) & 1023u) + offb];
        float4 B2 = sv[((wb >> 20) & 1023u) + offb];
        acc += vmask * pairPhi(A0, A1, A2, B0, B1, B2);
    }

    __shared__ float swarp[8];
    __shared__ float s_lb;
    int wid = j >> 5;
    float w = warpReduceSum(acc);
    if ((j & 31) == 0) swarp[wid] = w;
    __syncthreads();
    if (j == 0) {
        float t = 0.0f;
#pragma unroll
        for (int i = 0; i < 8; i++) t += swarp[i];
        s_lb = t;
    }
    __syncthreads();

    // ---- per-batch small loss partials, element-parallel over j ----
    float a[NRED];
#pragma unroll
    for (int i = 0; i < NRED; i++) a[i] = 0.0f;

    if (j == 0) {
        float lb = s_lb;
        a[0] = lb;
        a[1] = (lb != 0.0f) ? 1.0f : 0.0f;
    }

    float fint = ((__ldg(handed + b * 2) + __ldg(handed + b * 2 + 1)) == 2) ? 1.0f : 0.0f;
    if (j == 0) a[2] = fint;

    if (j < 10) {
        float d = betas[b * 10 + j] - betas[(BN + b) * 10 + j];
        a[3] = fint * d * d;
    }
    if (j < 3) {
        float d = (transl[b * 3 + j] - transl[(BN + b) * 3 + j]) -
                  (ttrans[b * 3 + j] - ttrans[(BN + b) * 3 + j]);
        a[4] = fint * d * d;
    }
    if (j < 63) {
        float d = (j3d[b * 63 + j] - j3d[(BN + b) * 63 + j]) -
                  (tj3d[b * 63 + j] - tj3d[(BN + b) * 63 + j]);
        a[5] = fint * d * d;
    }

#pragma unroll
    for (int h = 0; h < 2; h++) {
        int base = 6 + 7 * h;
        float m = (float)__ldg(valid + h * BN + b);
        if (j == 0) a[base + 0] = m;

        if (j < 3) {
            float d = go[(h * BN + b) * 3 + j] - tgo[(h * BN + b) * 3 + j];
            a[base + 1] = m * d * d;
        }
        if (j < 45) {
            float d = pose[(h * BN + b) * 45 + j] - tpose[(h * BN + b) * 45 + j];
            a[base + 2] = m * d * d;
        }
        if (j < 63) {
            const float* jo = j3d  + (size_t)(h * BN + b) * 63;
            const float* jt = tj3d + (size_t)(h * BN + b) * 63;
            float o = jo[j], t = jt[j];
            if (j >= 3) {
                int c = j % 3;
                float d = (o - jo[c]) * 1000.0f - (t - jt[c]) * 1000.0f;
                a[base + 3] = m * fabsf(d);
            }
            a[base + 4] = m * fabsf(o * 1000.0f - t * 1000.0f);
        }
        if (j < 10) {
            float d = betas[(h * BN + b) * 10 + j] - tshape[(h * BN + b) * 10 + j];
            a[base + 5] = m * d * d;
        }
        if (j < 3) {
            float d = transl[(h * BN + b) * 3 + j] - ttrans[(h * BN + b) * 3 + j];
            a[base + 6] = m * fabsf(d);
        }
    }

    if (j == 0) {
        const float* lg = logits + b * 4;
        float l0 = lg[0], l1 = lg[1], l2 = lg[2], l3 = lg[3];
        float mx = fmaxf(fmaxf(l0, l1), fmaxf(l2, l3));
        float se = __expf(l0 - mx) + __expf(l1 - mx) + __expf(l2 - mx) + __expf(l3 - mx);
        float lse = logf(se);
        int t = __ldg(ctgt + b);
        float lt = (t == 0) ? l0 : (t == 1) ? l1 : (t == 2) ? l2 : l3;
        float nll = -(lt - mx - lse);
        const float wts[4] = {1.0f, 30.0f, 30.0f, 10.0f};
        float wv = wts[t] * ((t != 0) ? 1.0f : 0.0f);
        a[20] = wv * nll;
        a[21] = wv;
    }

    // block-reduce the 22 slots (8 warps)
    __shared__ float red[NRED][8];
#pragma unroll
    for (int i = 0; i < NRED; i++) {
        float v = warpReduceSum(a[i]);
        if ((j & 31) == 0) red[i][wid] = v;
    }
    __syncthreads();
    if (j < NRED) {
        float t = 0.0f;
#pragma unroll
        for (int k = 0; k < 8; k++) t += red[j][k];
        g_part[j * BN + b] = t;
    }

    // ---- last block folds the final reduction ----
    __threadfence();
    __syncthreads();
    __shared__ bool isLast;
    if (j == 0)
        isLast = (atomicAdd(&g_cnt, 1u) == (unsigned)(gridDim.x - 1));
    __syncthreads();
    if (!isLast) return;
    __threadfence();  // acquire all blocks' g_part writes

    float r[NRED];
#pragma unroll
    for (int i = 0; i < NRED; i++)
        r[i] = g_part[i * BN + j] + g_part[i * BN + 256 + j];

    __syncthreads();  // reuse red[][] safely
#pragma unroll
    for (int i = 0; i < NRED; i++) {
        float v = warpReduceSum(r[i]);
        if ((j & 31) == 0) red[i][wid] = v;
    }
    __syncthreads();

    if (j == 0) {
        g_cnt = 0;  // reset for next graph replay
        float s[NRED];
#pragma unroll
        for (int i = 0; i < NRED; i++) {
            float t = 0.0f;
#pragma unroll
            for (int k = 0; k < 8; k++) t += red[i][k];
            s[i] = t;
        }
        auto il = [](float sum, float denom) -> float {
            return (denom > 0.0f) ? sum / fmaxf(denom, 1.0f) : 0.0f;
        };

        out[0] = (s[1] > 0.0f) ? (s[0] / fmaxf(s[1], 1.0f)) * 100.0f : 0.0f;
        float ic = s[2];
        out[1] = il(s[3], ic * 10.0f);
        out[2] = il(s[4], ic * 3.0f) * 100.0f;
        out[3] = il(s[5], ic * 63.0f) * 100.0f;

        float lgo = 0, lhp = 0, lrj = 0, lj3 = 0, lsh = 0, ltr = 0;
#pragma unroll
        for (int h = 0; h < 2; h++) {
            int base = 6 + 7 * h;
            float c = s[base + 0];
            lgo += il(s[base + 1], c * 3.0f)  * 10.0f;
            lhp += il(s[base + 2], c * 45.0f) * 10.0f;
            lrj += il(s[base + 3], c * 60.0f) * 0.01f;
            lj3 += il(s[base + 4], c * 63.0f) * 0.01f;
            lsh += il(s[base + 5], c * 10.0f) * 10.0f;
            ltr += il(s[base + 6], c * 3.0f)  * 10.0f;
        }
        out[4] = lgo;
        out[5] = lhp;
        out[6] = lrj;
        out[7] = lj3;
        out[8] = lsh;
        out[9] = ltr;
        out[10] = 0.0f;  // mse(x,x) == 0 exactly
        out[11] = s[20] / fmaxf(s[21], 1e-9f);
    }
}

extern "C" void kernel_launch(void* const* d_in, const int* in_sizes, int n_in,
                              void* d_out, int out_size) {
    const float* verts  = (const float*)d_in[0];
    const float* betas  = (const float*)d_in[1];
    const float* transl = (const float*)d_in[2];
    const float* j3d    = (const float*)d_in[3];
    const float* go     = (const float*)d_in[4];
    const float* pose   = (const float*)d_in[5];
    const float* ttrans = (const float*)d_in[6];
    const float* tj3d   = (const float*)d_in[7];
    const float* tgo    = (const float*)d_in[8];
    const float* tpose  = (const float*)d_in[9];
    const float* tshape = (const float*)d_in[10];
    const float* logits = (const float*)d_in[11];
    const int*   faces  = (const int*)d_in[12];
    const int*   cidx   = (const int*)d_in[13];
    const int*   handed = (const int*)d_in[14];
    const int*   valid  = (const int*)d_in[15];
    const int*   ctgt   = (const int*)d_in[16];

    fused_kernel<<<BN, 256, SMEM_BYTES>>>(verts, faces, cidx, betas, transl,
                                          j3d, go, pose, ttrans, tj3d, tgo,
                                          tpose, tshape, logits, handed, valid,
                                          ctgt, (float*)d_out);
}